// round 2
// baseline (speedup 1.0000x reference)
#include <cuda_runtime.h>
#include <math.h>

#define H 1024
#define V 50257
#define L 128

// ---- scratch (no allocations allowed), 16B-aligned for float4 access ----
__device__ __align__(16) float g_attn_scratch[L];   // logits, then weights
__device__ __align__(16) float g_attn_applied[H];
__device__ __align__(16) float g_x[H];              // relu(comb) output
__device__ __align__(16) float g_h[H];              // new hidden (aligned copy)
__device__ __align__(16) float g_logits[V + 3];
__device__ unsigned g_max_u;
__device__ float    g_sumexp;

__device__ __forceinline__ float warp_sum(float v) {
    #pragma unroll
    for (int o = 16; o; o >>= 1) v += __shfl_down_sync(0xffffffffu, v, o);
    return v;
}

__device__ __forceinline__ unsigned flip_f(float f) {
    unsigned u = __float_as_uint(f);
    return (u & 0x80000000u) ? ~u : (u | 0x80000000u);
}
__device__ __forceinline__ float unflip_f(unsigned u) {
    return (u & 0x80000000u) ? __uint_as_float(u ^ 0x80000000u)
                             : __uint_as_float(~u);
}

__global__ void k_init() {
    g_max_u = 0u;
    g_sumexp = 0.f;
}

// attn logits: 128 rows, block per row, dot of [embedded||h0] (2048) with attn_W row
__global__ void k_attn_logits(const int* __restrict__ tokens,
                              const float* __restrict__ emb,
                              const float* __restrict__ h0,
                              const float* __restrict__ attn_W,
                              const float* __restrict__ attn_b) {
    int l = blockIdx.x;
    const float4* erow = (const float4*)(emb + (long)tokens[0] * H);
    const float4* hrow = (const float4*)h0;
    const float4* w    = (const float4*)(attn_W + (long)l * 2 * H);
    float acc = 0.f;
    for (int i = threadIdx.x; i < 2 * H / 4; i += blockDim.x) {
        float4 wv = w[i];
        float4 xv = (i < H / 4) ? erow[i] : hrow[i - H / 4];
        acc += wv.x * xv.x + wv.y * xv.y + wv.z * xv.z + wv.w * xv.w;
    }
    __shared__ float s[8];
    acc = warp_sum(acc);
    if ((threadIdx.x & 31) == 0) s[threadIdx.x >> 5] = acc;
    __syncthreads();
    if (threadIdx.x == 0) {
        float v = 0.f;
        #pragma unroll
        for (int k = 0; k < 8; k++) v += s[k];
        g_attn_scratch[l] = v + attn_b[l];
    }
}

// softmax over 128 logits, single block; writes attn_weights output + scratch
__global__ void k_softmax(float* __restrict__ attn_w_out) {
    int t = threadIdx.x;
    float v = g_attn_scratch[t];
    __shared__ float sm[L];
    sm[t] = v; __syncthreads();
    for (int s = 64; s; s >>= 1) { if (t < s) sm[t] = fmaxf(sm[t], sm[t + s]); __syncthreads(); }
    float m = sm[0]; __syncthreads();
    float e = expf(v - m);
    sm[t] = e; __syncthreads();
    for (int s = 64; s; s >>= 1) { if (t < s) sm[t] += sm[t + s]; __syncthreads(); }
    float w = e / sm[0];
    attn_w_out[t]     = w;
    g_attn_scratch[t] = w;   // reuse as weights
}

// attn_applied[j] = sum_l w[l] * enc[l][j]
__global__ void k_attn_applied(const float* __restrict__ enc) {
    int j = blockIdx.x * blockDim.x + threadIdx.x;
    __shared__ float w[L];
    if (threadIdx.x < L) w[threadIdx.x] = g_attn_scratch[threadIdx.x];
    __syncthreads();
    float acc = 0.f;
    #pragma unroll 8
    for (int l = 0; l < L; l++) acc += w[l] * enc[l * H + j];
    g_attn_applied[j] = acc;
}

// x = relu(comb_W @ [embedded||attn_applied] + comb_b), warp per row
__global__ void k_comb(const int* __restrict__ tokens,
                       const float* __restrict__ emb,
                       const float* __restrict__ comb_W,
                       const float* __restrict__ comb_b) {
    int warp = threadIdx.x >> 5, lane = threadIdx.x & 31;
    int row = blockIdx.x * 8 + warp;
    const float4* erow = (const float4*)(emb + (long)tokens[0] * H);
    const float4* arow = (const float4*)g_attn_applied;
    const float4* w    = (const float4*)(comb_W + (long)row * 2 * H);
    float acc = 0.f;
    #pragma unroll
    for (int i = lane; i < 512; i += 32) {
        float4 wv = w[i];
        float4 xv = (i < 256) ? erow[i] : arow[i - 256];
        acc += wv.x * xv.x + wv.y * xv.y + wv.z * xv.z + wv.w * xv.w;
    }
    acc = warp_sum(acc);
    if (lane == 0) g_x[row] = fmaxf(acc + comb_b[row], 0.f);
}

// LSTM cell: block per hidden index j; 4 warps compute gates i,f,g,o
__global__ void k_lstm(const float* __restrict__ W_ih, const float* __restrict__ W_hh,
                       const float* __restrict__ b_ih, const float* __restrict__ b_hh,
                       const float* __restrict__ h0,   const float* __restrict__ c0,
                       float* __restrict__ h_out, float* __restrict__ c_out) {
    int j = blockIdx.x;
    int warp = threadIdx.x >> 5, lane = threadIdx.x & 31;
    int r = warp * H + j;  // gate row
    const float4* wi = (const float4*)(W_ih + (long)r * H);
    const float4* wh = (const float4*)(W_hh + (long)r * H);
    const float4* xv = (const float4*)g_x;
    const float4* hv = (const float4*)h0;
    float acc = 0.f;
    #pragma unroll
    for (int i = lane; i < 256; i += 32) {
        float4 a = wi[i], b = xv[i];
        acc += a.x * b.x + a.y * b.y + a.z * b.z + a.w * b.w;
        float4 cm = wh[i], d = hv[i];
        acc += cm.x * d.x + cm.y * d.y + cm.z * d.z + cm.w * d.w;
    }
    acc = warp_sum(acc);
    __shared__ float g[4];
    if (lane == 0) g[warp] = acc + b_ih[r] + b_hh[r];
    __syncthreads();
    if (threadIdx.x == 0) {
        float ig = 1.f / (1.f + expf(-g[0]));
        float fg = 1.f / (1.f + expf(-g[1]));
        float gg = tanhf(g[2]);
        float og = 1.f / (1.f + expf(-g[3]));
        float cn = fg * c0[j] + ig * gg;
        float hn = og * tanhf(cn);
        c_out[j] = cn;
        h_out[j] = hn;   // scalar store, any alignment OK
        g_h[j]   = hn;   // aligned copy for vectorized reads in k_out
    }
}

// output projection: warp per vocab row; also feeds global max via atomic
__global__ void k_out(const float* __restrict__ out_W,
                      const float* __restrict__ out_b) {
    __shared__ float4 sh4[H / 4];
    __shared__ float  smax[8];
    for (int i = threadIdx.x; i < H / 4; i += blockDim.x)
        sh4[i] = ((const float4*)g_h)[i];
    __syncthreads();
    int warp = threadIdx.x >> 5, lane = threadIdx.x & 31;
    int row = blockIdx.x * 8 + warp;
    float logit = -INFINITY;
    if (row < V) {
        const float4* w = (const float4*)(out_W + (long)row * H);
        float acc = 0.f;
        #pragma unroll
        for (int i = lane; i < 256; i += 32) {
            float4 a = w[i], b = sh4[i];
            acc += a.x * b.x + a.y * b.y + a.z * b.z + a.w * b.w;
        }
        acc = warp_sum(acc);
        if (lane == 0) {
            logit = acc + out_b[row];
            g_logits[row] = logit;
        }
    }
    if (lane == 0) smax[warp] = logit;
    __syncthreads();
    if (threadIdx.x == 0) {
        float m = smax[0];
        #pragma unroll
        for (int k = 1; k < 8; k++) m = fmaxf(m, smax[k]);
        atomicMax(&g_max_u, flip_f(m));
    }
}

__global__ void k_sumexp() {
    int v = blockIdx.x * blockDim.x + threadIdx.x;
    float m = unflip_f(g_max_u);
    float e = (v < V) ? expf(g_logits[v] - m) : 0.f;
    e = warp_sum(e);
    __shared__ float s[8];
    if ((threadIdx.x & 31) == 0) s[threadIdx.x >> 5] = e;
    __syncthreads();
    if (threadIdx.x == 0) {
        float t = 0.f;
        #pragma unroll
        for (int k = 0; k < 8; k++) t += s[k];
        atomicAdd(&g_sumexp, t);
    }
}

__global__ void k_final(float* __restrict__ out) {
    int v = blockIdx.x * blockDim.x + threadIdx.x;
    if (v >= V) return;
    float m = unflip_f(g_max_u);
    out[v] = g_logits[v] - m - logf(g_sumexp);
}

extern "C" void kernel_launch(void* const* d_in, const int* in_sizes, int n_in,
                              void* d_out, int out_size) {
    const int*   tokens = (const int*)  d_in[0];
    const float* h0     = (const float*)d_in[1];
    const float* c0     = (const float*)d_in[2];
    const float* enc    = (const float*)d_in[3];
    const float* emb    = (const float*)d_in[4];
    const float* attn_W = (const float*)d_in[5];
    const float* attn_b = (const float*)d_in[6];
    const float* comb_W = (const float*)d_in[7];
    const float* comb_b = (const float*)d_in[8];
    const float* W_ih   = (const float*)d_in[9];
    const float* W_hh   = (const float*)d_in[10];
    const float* b_ih   = (const float*)d_in[11];
    const float* b_hh   = (const float*)d_in[12];
    const float* out_W  = (const float*)d_in[13];
    const float* out_b  = (const float*)d_in[14];

    float* out    = (float*)d_out;          // [V] log-probs
    float* h_out  = out + V;                // [H]
    float* c_out  = out + V + H;            // [H]
    float* aw_out = out + V + 2 * H;        // [L]

    k_init        <<<1, 1>>>();
    k_attn_logits <<<L, 256>>>(tokens, emb, h0, attn_W, attn_b);
    k_softmax     <<<1, L>>>(aw_out);
    k_attn_applied<<<H / 256, 256>>>(enc);
    k_comb        <<<H / 8, 256>>>(tokens, emb, comb_W, comb_b);
    k_lstm        <<<H, 128>>>(W_ih, W_hh, b_ih, b_hh, h0, c0, h_out, c_out);
    k_out         <<<(V + 7) / 8, 256>>>(out_W, out_b);
    k_sumexp      <<<(V + 255) / 256, 256>>>();
    k_final       <<<(V + 255) / 256, 256>>>(out);
}

// round 3
// speedup vs baseline: 1.0035x; 1.0035x over previous
#include <cuda_runtime.h>
#include <math.h>

#define H 1024
#define V 50257
#define L 128
#define OUT_ROWS 16
#define GOUT ((V + OUT_ROWS - 1) / OUT_ROWS)   // 3142 blocks

// ---- scratch (no allocations allowed), 16B-aligned for float4 access ----
__device__ __align__(16) float g_attn_scratch[L];   // logits, then weights
__device__ __align__(16) float g_attn_applied[H];
__device__ __align__(16) float g_x[H];              // relu(comb) output
__device__ __align__(16) float g_h[H];              // new hidden (aligned copy)
__device__ __align__(16) float g_logits[V + 3];
__device__ __align__(16) float g_bmax[GOUT];
__device__ __align__(16) float g_bsum[GOUT];
__device__ float    g_logZ;
__device__ unsigned g_ctr_attn = 0;
__device__ unsigned g_ctr_out  = 0;

__device__ __forceinline__ float warp_sum(float v) {
    #pragma unroll
    for (int o = 16; o; o >>= 1) v += __shfl_down_sync(0xffffffffu, v, o);
    return v;
}
__device__ __forceinline__ float warp_max(float v) {
    #pragma unroll
    for (int o = 16; o; o >>= 1) v = fmaxf(v, __shfl_down_sync(0xffffffffu, v, o));
    return v;
}

// ---------------------------------------------------------------------------
// attn logits (block per row) + fused softmax in last arriving block
// ---------------------------------------------------------------------------
__global__ void k_attn(const int* __restrict__ tokens,
                       const float* __restrict__ emb,
                       const float* __restrict__ h0,
                       const float* __restrict__ attn_W,
                       const float* __restrict__ attn_b,
                       float* __restrict__ attn_w_out) {
    int l = blockIdx.x;
    const float4* erow = (const float4*)(emb + (long)tokens[0] * H);
    const float4* hrow = (const float4*)h0;
    const float4* w    = (const float4*)(attn_W + (long)l * 2 * H);
    float acc = 0.f;
    for (int i = threadIdx.x; i < 2 * H / 4; i += blockDim.x) {
        float4 wv = w[i];
        float4 xv = (i < H / 4) ? erow[i] : hrow[i - H / 4];
        acc += wv.x * xv.x + wv.y * xv.y + wv.z * xv.z + wv.w * xv.w;
    }
    __shared__ float s[8];
    acc = warp_sum(acc);
    if ((threadIdx.x & 31) == 0) s[threadIdx.x >> 5] = acc;
    __syncthreads();
    __shared__ unsigned is_last;
    if (threadIdx.x == 0) {
        float v = 0.f;
        #pragma unroll
        for (int k = 0; k < 8; k++) v += s[k];
        g_attn_scratch[l] = v + attn_b[l];
        __threadfence();
        is_last = (atomicAdd(&g_ctr_attn, 1u) == L - 1);
    }
    __syncthreads();
    if (!is_last) return;

    // ---- last block: softmax over 128 logits ----
    __threadfence();
    __shared__ float sm[L];
    int t = threadIdx.x;
    float v = 0.f;
    if (t < L) { v = g_attn_scratch[t]; sm[t] = v; }
    __syncthreads();
    if (t < L) {
        for (int st = 64; st; st >>= 1) { if (t < st) sm[t] = fmaxf(sm[t], sm[t + st]); __syncthreads(); }
    } else { for (int st = 64; st; st >>= 1) __syncthreads(); }
    float m = sm[0]; __syncthreads();
    float e = (t < L) ? expf(v - m) : 0.f;
    if (t < L) sm[t] = e;
    __syncthreads();
    if (t < L) {
        for (int st = 64; st; st >>= 1) { if (t < st) sm[t] += sm[t + st]; __syncthreads(); }
    } else { for (int st = 64; st; st >>= 1) __syncthreads(); }
    if (t < L) {
        float wgt = e / sm[0];
        attn_w_out[t]     = wgt;
        g_attn_scratch[t] = wgt;
    }
    if (t == 0) g_ctr_attn = 0;   // reset for next graph replay
}

// ---------------------------------------------------------------------------
// attn_applied[j] = sum_l w[l] * enc[l][j]   — 32 blocks, 8 l-groups each
// ---------------------------------------------------------------------------
__global__ void k_attn_applied(const float* __restrict__ enc) {
    int t  = threadIdx.x;
    int jl = t & 31, lg = t >> 5;              // 32 j's x 8 l-groups
    int j  = blockIdx.x * 32 + jl;
    float acc = 0.f;
    #pragma unroll
    for (int k = 0; k < 16; k++) {
        int l = lg * 16 + k;
        acc += g_attn_scratch[l] * enc[l * H + j];
    }
    __shared__ float s[8][32];
    s[lg][jl] = acc;
    __syncthreads();
    if (lg == 0) {
        float v = acc;
        #pragma unroll
        for (int k = 1; k < 8; k++) v += s[k][jl];
        g_attn_applied[j] = v;
    }
}

// ---------------------------------------------------------------------------
// x = relu(comb_W @ [embedded||attn_applied] + comb_b), warp per row
// ---------------------------------------------------------------------------
__global__ void k_comb(const int* __restrict__ tokens,
                       const float* __restrict__ emb,
                       const float* __restrict__ comb_W,
                       const float* __restrict__ comb_b) {
    int warp = threadIdx.x >> 5, lane = threadIdx.x & 31;
    int row = blockIdx.x * 8 + warp;
    const float4* erow = (const float4*)(emb + (long)tokens[0] * H);
    const float4* arow = (const float4*)g_attn_applied;
    const float4* w    = (const float4*)(comb_W + (long)row * 2 * H);
    float acc = 0.f;
    #pragma unroll
    for (int i = lane; i < 512; i += 32) {
        float4 wv = w[i];
        float4 xv = (i < 256) ? erow[i] : arow[i - 256];
        acc += wv.x * xv.x + wv.y * xv.y + wv.z * xv.z + wv.w * xv.w;
    }
    acc = warp_sum(acc);
    if (lane == 0) g_x[row] = fmaxf(acc + comb_b[row], 0.f);
}

// ---------------------------------------------------------------------------
// LSTM cell: block per hidden index j; 4 warps compute gates i,f,g,o
// ---------------------------------------------------------------------------
__global__ void k_lstm(const float* __restrict__ W_ih, const float* __restrict__ W_hh,
                       const float* __restrict__ b_ih, const float* __restrict__ b_hh,
                       const float* __restrict__ h0,   const float* __restrict__ c0,
                       float* __restrict__ h_out, float* __restrict__ c_out) {
    int j = blockIdx.x;
    int warp = threadIdx.x >> 5, lane = threadIdx.x & 31;
    int r = warp * H + j;
    const float4* wi = (const float4*)(W_ih + (long)r * H);
    const float4* wh = (const float4*)(W_hh + (long)r * H);
    const float4* xv = (const float4*)g_x;
    const float4* hv = (const float4*)h0;
    float acc = 0.f;
    #pragma unroll
    for (int i = lane; i < 256; i += 32) {
        float4 a = wi[i], b = xv[i];
        acc += a.x * b.x + a.y * b.y + a.z * b.z + a.w * b.w;
        float4 cm = wh[i], d = hv[i];
        acc += cm.x * d.x + cm.y * d.y + cm.z * d.z + cm.w * d.w;
    }
    acc = warp_sum(acc);
    __shared__ float g[4];
    if (lane == 0) g[warp] = acc + b_ih[r] + b_hh[r];
    __syncthreads();
    if (threadIdx.x == 0) {
        float ig = 1.f / (1.f + expf(-g[0]));
        float fg = 1.f / (1.f + expf(-g[1]));
        float gg = tanhf(g[2]);
        float og = 1.f / (1.f + expf(-g[3]));
        float cn = fg * c0[j] + ig * gg;
        float hn = og * tanhf(cn);
        c_out[j] = cn;
        h_out[j] = hn;   // scalar store, any alignment OK
        g_h[j]   = hn;   // aligned copy for vectorized reads in k_out
    }
}

// ---------------------------------------------------------------------------
// output projection, 16 rows/block (512 thr), fused logZ via last-block reduce
// ---------------------------------------------------------------------------
__global__ void __launch_bounds__(512) k_out(const float* __restrict__ out_W,
                                             const float* __restrict__ out_b) {
    __shared__ float4 sh4[H / 4];
    __shared__ float  slog[OUT_ROWS];
    for (int i = threadIdx.x; i < H / 4; i += blockDim.x)
        sh4[i] = ((const float4*)g_h)[i];
    __syncthreads();
    int warp = threadIdx.x >> 5, lane = threadIdx.x & 31;
    int row = blockIdx.x * OUT_ROWS + warp;
    float logit = -INFINITY;
    if (row < V) {
        const float4* w = (const float4*)(out_W + (long)row * H);
        float acc = 0.f;
        #pragma unroll
        for (int i = lane; i < 256; i += 32) {
            float4 a = w[i], b = sh4[i];
            acc += a.x * b.x + a.y * b.y + a.z * b.z + a.w * b.w;
        }
        acc = warp_sum(acc);
        if (lane == 0) {
            logit = acc + out_b[row];
            g_logits[row] = logit;
        }
    }
    if (lane == 0) slog[warp] = logit;
    __syncthreads();
    __shared__ unsigned is_last;
    if (threadIdx.x == 0) {
        float m = slog[0];
        #pragma unroll
        for (int k = 1; k < OUT_ROWS; k++) m = fmaxf(m, slog[k]);
        float s = 0.f;
        #pragma unroll
        for (int k = 0; k < OUT_ROWS; k++) s += expf(slog[k] - m);  // exp(-inf)=0 for pad rows
        g_bmax[blockIdx.x] = m;
        g_bsum[blockIdx.x] = s;
        __threadfence();
        is_last = (atomicAdd(&g_ctr_out, 1u) == GOUT - 1);
    }
    __syncthreads();
    if (!is_last) return;

    // ---- last block: reduce 3142 (max,sum) pairs ----
    __threadfence();
    int t = threadIdx.x;
    float m = -INFINITY;
    for (int k = t; k < GOUT; k += 512) m = fmaxf(m, g_bmax[k]);
    __shared__ float sred[16];
    m = warp_max(m);
    if (lane == 0) sred[warp] = m;
    __syncthreads();
    if (t == 0) {
        float mm = sred[0];
        #pragma unroll
        for (int k = 1; k < 16; k++) mm = fmaxf(mm, sred[k]);
        sred[0] = mm;
    }
    __syncthreads();
    m = sred[0];
    __syncthreads();
    float s = 0.f;
    for (int k = t; k < GOUT; k += 512) s += g_bsum[k] * expf(g_bmax[k] - m);
    s = warp_sum(s);
    if (lane == 0) sred[warp] = s;
    __syncthreads();
    if (t == 0) {
        float ss = 0.f;
        #pragma unroll
        for (int k = 0; k < 16; k++) ss += sred[k];
        g_logZ = m + logf(ss);
        g_ctr_out = 0;   // reset for next graph replay
    }
}

__global__ void k_final(float* __restrict__ out) {
    int v = blockIdx.x * blockDim.x + threadIdx.x;
    if (v >= V) return;
    out[v] = g_logits[v] - g_logZ;
}

extern "C" void kernel_launch(void* const* d_in, const int* in_sizes, int n_in,
                              void* d_out, int out_size) {
    const int*   tokens = (const int*)  d_in[0];
    const float* h0     = (const float*)d_in[1];
    const float* c0     = (const float*)d_in[2];
    const float* enc    = (const float*)d_in[3];
    const float* emb    = (const float*)d_in[4];
    const float* attn_W = (const float*)d_in[5];
    const float* attn_b = (const float*)d_in[6];
    const float* comb_W = (const float*)d_in[7];
    const float* comb_b = (const float*)d_in[8];
    const float* W_ih   = (const float*)d_in[9];
    const float* W_hh   = (const float*)d_in[10];
    const float* b_ih   = (const float*)d_in[11];
    const float* b_hh   = (const float*)d_in[12];
    const float* out_W  = (const float*)d_in[13];
    const float* out_b  = (const float*)d_in[14];

    float* out    = (float*)d_out;          // [V] log-probs
    float* h_out  = out + V;                // [H]
    float* c_out  = out + V + H;            // [H]
    float* aw_out = out + V + 2 * H;        // [L]

    k_attn        <<<L, 256>>>(tokens, emb, h0, attn_W, attn_b, aw_out);
    k_attn_applied<<<H / 32, 256>>>(enc);
    k_comb        <<<H / 8, 256>>>(tokens, emb, comb_W, comb_b);
    k_lstm        <<<H, 128>>>(W_ih, W_hh, b_ih, b_hh, h0, c0, h_out, c_out);
    k_out         <<<GOUT, 512>>>(out_W, out_b);
    k_final       <<<(V + 511) / 512, 512>>>(out);
}

// round 4
// speedup vs baseline: 1.0900x; 1.0862x over previous
#include <cuda_runtime.h>
#include <math.h>

#define H 1024
#define V 50257
#define L 128
#define OUT_ROWS 16
#define GOUT ((V + OUT_ROWS - 1) / OUT_ROWS)   // 3142 blocks

// ---- scratch (no allocations allowed), 16B-aligned for float4 access ----
__device__ __align__(16) float g_attn_scratch[L];   // logits, then weights
__device__ __align__(16) float g_attn_applied[H];
__device__ __align__(16) float g_x[H];              // relu(comb) output
__device__ __align__(16) float g_h[H];              // new hidden (aligned copy)
__device__ __align__(16) float g_logits[V + 3];
__device__ __align__(16) float g_bmax[GOUT];
__device__ __align__(16) float g_bsum[GOUT];
__device__ float    g_logZ;
__device__ unsigned g_ctr_attn = 0;
__device__ unsigned g_ctr_out  = 0;

__device__ __forceinline__ float warp_sum(float v) {
    #pragma unroll
    for (int o = 16; o; o >>= 1) v += __shfl_down_sync(0xffffffffu, v, o);
    return v;
}
__device__ __forceinline__ float warp_max(float v) {
    #pragma unroll
    for (int o = 16; o; o >>= 1) v = fmaxf(v, __shfl_down_sync(0xffffffffu, v, o));
    return v;
}
__device__ __forceinline__ float dot4(float4 a, float4 b) {
    return a.x * b.x + a.y * b.y + a.z * b.z + a.w * b.w;
}

// ---------------------------------------------------------------------------
// attn logits (block per row) + fused softmax in last arriving block
// ---------------------------------------------------------------------------
__global__ void k_attn(const int* __restrict__ tokens,
                       const float* __restrict__ emb,
                       const float* __restrict__ h0,
                       const float* __restrict__ attn_W,
                       const float* __restrict__ attn_b,
                       float* __restrict__ attn_w_out) {
    int l = blockIdx.x;
    const float4* erow = (const float4*)(emb + (long)tokens[0] * H);
    const float4* hrow = (const float4*)h0;
    const float4* w    = (const float4*)(attn_W + (long)l * 2 * H);
    float acc = 0.f;
    for (int i = threadIdx.x; i < 2 * H / 4; i += blockDim.x) {
        float4 wv = __ldcs(w + i);
        float4 xv = (i < H / 4) ? erow[i] : hrow[i - H / 4];
        acc += dot4(wv, xv);
    }
    __shared__ float s[8];
    acc = warp_sum(acc);
    if ((threadIdx.x & 31) == 0) s[threadIdx.x >> 5] = acc;
    __syncthreads();
    __shared__ unsigned is_last;
    if (threadIdx.x == 0) {
        float v = 0.f;
        #pragma unroll
        for (int k = 0; k < 8; k++) v += s[k];
        g_attn_scratch[l] = v + attn_b[l];
        __threadfence();
        is_last = (atomicAdd(&g_ctr_attn, 1u) == L - 1);
    }
    __syncthreads();
    if (!is_last) return;

    // ---- last block: softmax over 128 logits ----
    __threadfence();
    __shared__ float sm[L];
    int t = threadIdx.x;
    float v = 0.f;
    if (t < L) { v = g_attn_scratch[t]; sm[t] = v; }
    __syncthreads();
    if (t < L) {
        for (int st = 64; st; st >>= 1) { if (t < st) sm[t] = fmaxf(sm[t], sm[t + st]); __syncthreads(); }
    } else { for (int st = 64; st; st >>= 1) __syncthreads(); }
    float m = sm[0]; __syncthreads();
    float e = (t < L) ? expf(v - m) : 0.f;
    if (t < L) sm[t] = e;
    __syncthreads();
    if (t < L) {
        for (int st = 64; st; st >>= 1) { if (t < st) sm[t] += sm[t + st]; __syncthreads(); }
    } else { for (int st = 64; st; st >>= 1) __syncthreads(); }
    if (t < L) {
        float wgt = e / sm[0];
        attn_w_out[t]     = wgt;
        g_attn_scratch[t] = wgt;
    }
    if (t == 0) g_ctr_attn = 0;   // reset for next graph replay
}

// ---------------------------------------------------------------------------
// attn_applied[j] = sum_l w[l] * enc[l][j]   — 32 blocks, 8 l-groups each
// ---------------------------------------------------------------------------
__global__ void k_attn_applied(const float* __restrict__ enc) {
    int t  = threadIdx.x;
    int jl = t & 31, lg = t >> 5;              // 32 j's x 8 l-groups
    int j  = blockIdx.x * 32 + jl;
    float acc = 0.f;
    #pragma unroll
    for (int k = 0; k < 16; k++) {
        int l = lg * 16 + k;
        acc += g_attn_scratch[l] * enc[l * H + j];
    }
    __shared__ float s[8][32];
    s[lg][jl] = acc;
    __syncthreads();
    if (lg == 0) {
        float v = acc;
        #pragma unroll
        for (int k = 1; k < 8; k++) v += s[k][jl];
        g_attn_applied[j] = v;
    }
}

// ---------------------------------------------------------------------------
// x = relu(comb_W @ [embedded||attn_applied] + comb_b), warp per row
// ---------------------------------------------------------------------------
__global__ void k_comb(const int* __restrict__ tokens,
                       const float* __restrict__ emb,
                       const float* __restrict__ comb_W,
                       const float* __restrict__ comb_b) {
    int warp = threadIdx.x >> 5, lane = threadIdx.x & 31;
    int row = blockIdx.x * 8 + warp;
    const float4* erow = (const float4*)(emb + (long)tokens[0] * H);
    const float4* arow = (const float4*)g_attn_applied;
    const float4* w    = (const float4*)(comb_W + (long)row * 2 * H);
    float acc = 0.f;
    #pragma unroll
    for (int i = lane; i < 512; i += 32) {
        float4 wv = __ldcs(w + i);
        float4 xv = (i < 256) ? erow[i] : arow[i - 256];
        acc += dot4(wv, xv);
    }
    acc = warp_sum(acc);
    if (lane == 0) g_x[row] = fmaxf(acc + comb_b[row], 0.f);
}

// ---------------------------------------------------------------------------
// LSTM cell: 512 blocks x 256 thr; block handles 2 hidden units (8 gate rows).
// x and h staged in smem once per block; warp w -> gate (w&3), unit (w>>2).
// ---------------------------------------------------------------------------
__global__ void __launch_bounds__(256) k_lstm(
        const float* __restrict__ W_ih, const float* __restrict__ W_hh,
        const float* __restrict__ b_ih, const float* __restrict__ b_hh,
        const float* __restrict__ h0,   const float* __restrict__ c0,
        float* __restrict__ h_out, float* __restrict__ c_out) {
    int tid  = threadIdx.x;
    int warp = tid >> 5, lane = tid & 31;
    int jj   = warp >> 2;            // 0..1 : which hidden unit in this block
    int gate = warp & 3;             // 0..3 : i,f,g,o
    int j    = blockIdx.x * 2 + jj;
    int r    = gate * H + j;

    __shared__ float4 sx[H / 4];
    __shared__ float4 sh[H / 4];
    sx[tid] = ((const float4*)g_x)[tid];
    sh[tid] = ((const float4*)h0)[tid];
    __syncthreads();

    const float4* wi = (const float4*)(W_ih + (long)r * H);
    const float4* wh = (const float4*)(W_hh + (long)r * H);
    float a1 = 0.f, a2 = 0.f;
    #pragma unroll
    for (int i = lane; i < 256; i += 32) {
        float4 a = __ldcs(wi + i);
        a1 += dot4(a, sx[i]);
        float4 b = __ldcs(wh + i);
        a2 += dot4(b, sh[i]);
    }
    float acc = warp_sum(a1 + a2);
    __shared__ float g[2][4];
    if (lane == 0) g[jj][gate] = acc + b_ih[r] + b_hh[r];
    __syncthreads();
    if (tid < 2) {
        int jd = blockIdx.x * 2 + tid;
        float ig = 1.f / (1.f + expf(-g[tid][0]));
        float fg = 1.f / (1.f + expf(-g[tid][1]));
        float gg = tanhf(g[tid][2]);
        float og = 1.f / (1.f + expf(-g[tid][3]));
        float cn = fg * c0[jd] + ig * gg;
        float hn = og * tanhf(cn);
        c_out[jd] = cn;
        h_out[jd] = hn;
        g_h[jd]   = hn;
    }
}

// ---------------------------------------------------------------------------
// output projection: 256 thr/block, 8 warps, 2 rows per warp (16 rows/block).
// 16 independent streaming loads in flight per thread. Fused logZ reduction.
// ---------------------------------------------------------------------------
__global__ void __launch_bounds__(256) k_out(const float* __restrict__ out_W,
                                             const float* __restrict__ out_b) {
    __shared__ float4 sh4[H / 4];
    __shared__ float  slog[OUT_ROWS];
    sh4[threadIdx.x] = ((const float4*)g_h)[threadIdx.x];
    __syncthreads();

    int warp = threadIdx.x >> 5, lane = threadIdx.x & 31;
    int row0 = blockIdx.x * OUT_ROWS + warp * 2;
    int row1 = row0 + 1;
    const float4* w0 = (const float4*)(out_W + (long)row0 * H);
    const float4* w1 = (const float4*)(out_W + (long)row1 * H);
    bool v0 = row0 < V, v1 = row1 < V;

    float a0 = 0.f, a1 = 0.f;
    #pragma unroll
    for (int i = lane; i < 256; i += 32) {
        float4 hv = sh4[i];
        if (v0) a0 += dot4(__ldcs(w0 + i), hv);
        if (v1) a1 += dot4(__ldcs(w1 + i), hv);
    }
    a0 = warp_sum(a0);
    a1 = warp_sum(a1);
    if (lane == 0) {
        float l0 = v0 ? a0 + out_b[row0] : -INFINITY;
        float l1 = v1 ? a1 + out_b[row1] : -INFINITY;
        if (v0) g_logits[row0] = l0;
        if (v1) g_logits[row1] = l1;
        slog[warp * 2]     = l0;
        slog[warp * 2 + 1] = l1;
    }
    __syncthreads();
    __shared__ unsigned is_last;
    if (threadIdx.x == 0) {
        float m = slog[0];
        #pragma unroll
        for (int k = 1; k < OUT_ROWS; k++) m = fmaxf(m, slog[k]);
        float s = 0.f;
        #pragma unroll
        for (int k = 0; k < OUT_ROWS; k++) s += expf(slog[k] - m);
        g_bmax[blockIdx.x] = m;
        g_bsum[blockIdx.x] = s;
        __threadfence();
        is_last = (atomicAdd(&g_ctr_out, 1u) == GOUT - 1);
    }
    __syncthreads();
    if (!is_last) return;

    // ---- last block: reduce 3142 (max,sum) pairs ----
    __threadfence();
    int t = threadIdx.x;
    float m = -INFINITY;
    for (int k = t; k < GOUT; k += 256) m = fmaxf(m, g_bmax[k]);
    __shared__ float sred[8];
    m = warp_max(m);
    if (lane == 0) sred[warp] = m;
    __syncthreads();
    if (t == 0) {
        float mm = sred[0];
        #pragma unroll
        for (int k = 1; k < 8; k++) mm = fmaxf(mm, sred[k]);
        sred[0] = mm;
    }
    __syncthreads();
    m = sred[0];
    __syncthreads();
    float s = 0.f;
    for (int k = t; k < GOUT; k += 256) s += g_bsum[k] * expf(g_bmax[k] - m);
    s = warp_sum(s);
    if (lane == 0) sred[warp] = s;
    __syncthreads();
    if (t == 0) {
        float ss = 0.f;
        #pragma unroll
        for (int k = 0; k < 8; k++) ss += sred[k];
        g_logZ = m + logf(ss);
        g_ctr_out = 0;   // reset for next graph replay
    }
}

__global__ void k_final(float* __restrict__ out) {
    int v = blockIdx.x * blockDim.x + threadIdx.x;
    if (v >= V) return;
    out[v] = g_logits[v] - g_logZ;
}

extern "C" void kernel_launch(void* const* d_in, const int* in_sizes, int n_in,
                              void* d_out, int out_size) {
    const int*   tokens = (const int*)  d_in[0];
    const float* h0     = (const float*)d_in[1];
    const float* c0     = (const float*)d_in[2];
    const float* enc    = (const float*)d_in[3];
    const float* emb    = (const float*)d_in[4];
    const float* attn_W = (const float*)d_in[5];
    const float* attn_b = (const float*)d_in[6];
    const float* comb_W = (const float*)d_in[7];
    const float* comb_b = (const float*)d_in[8];
    const float* W_ih   = (const float*)d_in[9];
    const float* W_hh   = (const float*)d_in[10];
    const float* b_ih   = (const float*)d_in[11];
    const float* b_hh   = (const float*)d_in[12];
    const float* out_W  = (const float*)d_in[13];
    const float* out_b  = (const float*)d_in[14];

    float* out    = (float*)d_out;          // [V] log-probs
    float* h_out  = out + V;                // [H]
    float* c_out  = out + V + H;            // [H]
    float* aw_out = out + V + 2 * H;        // [L]

    k_attn        <<<L, 256>>>(tokens, emb, h0, attn_W, attn_b, aw_out);
    k_attn_applied<<<H / 32, 256>>>(enc);
    k_comb        <<<H / 8, 256>>>(tokens, emb, comb_W, comb_b);
    k_lstm        <<<H / 2, 256>>>(W_ih, W_hh, b_ih, b_hh, h0, c0, h_out, c_out);
    k_out         <<<GOUT, 256>>>(out_W, out_b);
    k_final       <<<(V + 511) / 512, 512>>>(out);
}

// round 5
// speedup vs baseline: 1.0951x; 1.0047x over previous
#include <cuda_runtime.h>
#include <math.h>

#define H 1024
#define V 50257
#define L 128
#define OUT_ROWS 16
#define GOUT ((V + OUT_ROWS - 1) / OUT_ROWS)   // 3142 blocks

// ---- scratch (no allocations allowed), 16B-aligned for float4 access ----
__device__ __align__(16) float g_attn_scratch[L];   // logits, then weights
__device__ __align__(16) float g_attn_applied[H];
__device__ __align__(16) float g_x[H];              // relu(comb) output
__device__ __align__(16) float g_h[H];              // new hidden (aligned copy)
__device__ __align__(16) float g_logits[V + 3];
__device__ __align__(16) float g_bmax[GOUT];
__device__ __align__(16) float g_bsum[GOUT];
__device__ float    g_logZ;
__device__ unsigned g_ctr_attn = 0;
__device__ unsigned g_ctr_out  = 0;

__device__ __forceinline__ float warp_sum(float v) {
    #pragma unroll
    for (int o = 16; o; o >>= 1) v += __shfl_down_sync(0xffffffffu, v, o);
    return v;
}
__device__ __forceinline__ float warp_max(float v) {
    #pragma unroll
    for (int o = 16; o; o >>= 1) v = fmaxf(v, __shfl_down_sync(0xffffffffu, v, o));
    return v;
}
__device__ __forceinline__ float dot4(float4 a, float4 b) {
    return a.x * b.x + a.y * b.y + a.z * b.z + a.w * b.w;
}

// ---------------------------------------------------------------------------
// attn logits (block per row) + fused softmax in last arriving block
// ---------------------------------------------------------------------------
__global__ void k_attn(const int* __restrict__ tokens,
                       const float* __restrict__ emb,
                       const float* __restrict__ h0,
                       const float* __restrict__ attn_W,
                       const float* __restrict__ attn_b,
                       float* __restrict__ attn_w_out) {
    int l = blockIdx.x;
    const float4* erow = (const float4*)(emb + (long)tokens[0] * H);
    const float4* hrow = (const float4*)h0;
    const float4* w    = (const float4*)(attn_W + (long)l * 2 * H);
    float acc = 0.f;
    for (int i = threadIdx.x; i < 2 * H / 4; i += blockDim.x) {
        float4 wv = __ldcs(w + i);
        float4 xv = (i < H / 4) ? erow[i] : hrow[i - H / 4];
        acc += dot4(wv, xv);
    }
    __shared__ float s[8];
    acc = warp_sum(acc);
    if ((threadIdx.x & 31) == 0) s[threadIdx.x >> 5] = acc;
    __syncthreads();
    __shared__ unsigned is_last;
    if (threadIdx.x == 0) {
        float v = 0.f;
        #pragma unroll
        for (int k = 0; k < 8; k++) v += s[k];
        g_attn_scratch[l] = v + attn_b[l];
        __threadfence();
        is_last = (atomicAdd(&g_ctr_attn, 1u) == L - 1);
    }
    __syncthreads();
    if (!is_last) return;

    // ---- last block: softmax over 128 logits ----
    __threadfence();
    __shared__ float sm[L];
    int t = threadIdx.x;
    float v = 0.f;
    if (t < L) { v = g_attn_scratch[t]; sm[t] = v; }
    __syncthreads();
    if (t < L) {
        for (int st = 64; st; st >>= 1) { if (t < st) sm[t] = fmaxf(sm[t], sm[t + st]); __syncthreads(); }
    } else { for (int st = 64; st; st >>= 1) __syncthreads(); }
    float m = sm[0]; __syncthreads();
    float e = (t < L) ? expf(v - m) : 0.f;
    if (t < L) sm[t] = e;
    __syncthreads();
    if (t < L) {
        for (int st = 64; st; st >>= 1) { if (t < st) sm[t] += sm[t + st]; __syncthreads(); }
    } else { for (int st = 64; st; st >>= 1) __syncthreads(); }
    if (t < L) {
        float wgt = e / sm[0];
        attn_w_out[t]     = wgt;
        g_attn_scratch[t] = wgt;
    }
    if (t == 0) g_ctr_attn = 0;   // reset for next graph replay
}

// ---------------------------------------------------------------------------
// attn_applied[j] = sum_l w[l] * enc[l][j]
// ---------------------------------------------------------------------------
__global__ void k_attn_applied(const float* __restrict__ enc) {
    int t  = threadIdx.x;
    int jl = t & 31, lg = t >> 5;
    int j  = blockIdx.x * 32 + jl;
    float acc = 0.f;
    #pragma unroll
    for (int k = 0; k < 16; k++) {
        int l = lg * 16 + k;
        acc += g_attn_scratch[l] * enc[l * H + j];
    }
    __shared__ float s[8][32];
    s[lg][jl] = acc;
    __syncthreads();
    if (lg == 0) {
        float v = acc;
        #pragma unroll
        for (int k = 1; k < 8; k++) v += s[k][jl];
        g_attn_applied[j] = v;
    }
}

// ---------------------------------------------------------------------------
// x = relu(comb_W @ [embedded||attn_applied] + comb_b), warp per row
// ---------------------------------------------------------------------------
__global__ void k_comb(const int* __restrict__ tokens,
                       const float* __restrict__ emb,
                       const float* __restrict__ comb_W,
                       const float* __restrict__ comb_b) {
    int warp = threadIdx.x >> 5, lane = threadIdx.x & 31;
    int row = blockIdx.x * 8 + warp;
    const float4* erow = (const float4*)(emb + (long)tokens[0] * H);
    const float4* arow = (const float4*)g_attn_applied;
    const float4* w    = (const float4*)(comb_W + (long)row * 2 * H);
    float4 wr[16];
    #pragma unroll
    for (int k = 0; k < 16; k++) wr[k] = __ldcs(w + lane + 32 * k);
    float acc = 0.f;
    #pragma unroll
    for (int k = 0; k < 16; k++) {
        int i = lane + 32 * k;
        float4 xv = (i < 256) ? erow[i] : arow[i - 256];
        acc += dot4(wr[k], xv);
    }
    acc = warp_sum(acc);
    if (lane == 0) g_x[row] = fmaxf(acc + comb_b[row], 0.f);
}

// ---------------------------------------------------------------------------
// LSTM cell: 1024 blocks x 128 thr (4 warps). Block handles 1 hidden unit.
// Warp g computes gate-row g: stages ALL 16 float4 weight loads (wi+wh) in
// registers before any FMA -> max memory-level parallelism.
// ---------------------------------------------------------------------------
__global__ void __launch_bounds__(128) k_lstm(
        const float* __restrict__ W_ih, const float* __restrict__ W_hh,
        const float* __restrict__ b_ih, const float* __restrict__ b_hh,
        const float* __restrict__ h0,   const float* __restrict__ c0,
        float* __restrict__ h_out, float* __restrict__ c_out) {
    int tid  = threadIdx.x;
    int gate = tid >> 5, lane = tid & 31;
    int j    = blockIdx.x;
    int r    = gate * H + j;

    const float4* wi = (const float4*)(W_ih + (long)r * H);
    const float4* wh = (const float4*)(W_hh + (long)r * H);

    // stage all weight loads first (independent, fill the memory pipe)
    float4 va[8], vb[8];
    #pragma unroll
    for (int k = 0; k < 8; k++) va[k] = __ldcs(wi + lane + 32 * k);
    #pragma unroll
    for (int k = 0; k < 8; k++) vb[k] = __ldcs(wh + lane + 32 * k);

    __shared__ float4 sx[H / 4];
    __shared__ float4 sh[H / 4];
    #pragma unroll
    for (int k = 0; k < 2; k++) {
        sx[tid + 128 * k] = ((const float4*)g_x)[tid + 128 * k];
        sh[tid + 128 * k] = ((const float4*)h0)[tid + 128 * k];
    }
    __syncthreads();

    float a1 = 0.f, a2 = 0.f;
    #pragma unroll
    for (int k = 0; k < 8; k++) {
        a1 += dot4(va[k], sx[lane + 32 * k]);
        a2 += dot4(vb[k], sh[lane + 32 * k]);
    }
    float acc = warp_sum(a1 + a2);
    __shared__ float g[4];
    if (lane == 0) g[gate] = acc + b_ih[r] + b_hh[r];
    __syncthreads();
    if (tid == 0) {
        float ig = 1.f / (1.f + expf(-g[0]));
        float fg = 1.f / (1.f + expf(-g[1]));
        float gg = tanhf(g[2]);
        float og = 1.f / (1.f + expf(-g[3]));
        float cn = fg * c0[j] + ig * gg;
        float hn = og * tanhf(cn);
        c_out[j] = cn;
        h_out[j] = hn;
        g_h[j]   = hn;
    }
}

// ---------------------------------------------------------------------------
// output projection: 256 thr/block, 2 rows/warp, ALL 16 loads staged in regs.
// OOB rows use clamped pointers (in-bounds loads) + masked logits.
// Fused logZ via last-block reduction.
// ---------------------------------------------------------------------------
__global__ void __launch_bounds__(256) k_out(const float* __restrict__ out_W,
                                             const float* __restrict__ out_b) {
    __shared__ float4 sh4[H / 4];
    __shared__ float  slog[OUT_ROWS];
    sh4[threadIdx.x] = ((const float4*)g_h)[threadIdx.x];
    __syncthreads();

    int warp = threadIdx.x >> 5, lane = threadIdx.x & 31;
    int row0 = blockIdx.x * OUT_ROWS + warp * 2;
    int row1 = row0 + 1;
    bool v0 = row0 < V, v1 = row1 < V;
    int r0c = v0 ? row0 : V - 1;
    int r1c = v1 ? row1 : V - 1;
    const float4* w0 = (const float4*)(out_W + (long)r0c * H);
    const float4* w1 = (const float4*)(out_W + (long)r1c * H);

    float4 wa[8], wb[8];
    #pragma unroll
    for (int k = 0; k < 8; k++) wa[k] = __ldcs(w0 + lane + 32 * k);
    #pragma unroll
    for (int k = 0; k < 8; k++) wb[k] = __ldcs(w1 + lane + 32 * k);

    float a0 = 0.f, a1 = 0.f;
    #pragma unroll
    for (int k = 0; k < 8; k++) {
        float4 hv = sh4[lane + 32 * k];
        a0 += dot4(wa[k], hv);
        a1 += dot4(wb[k], hv);
    }
    a0 = warp_sum(a0);
    a1 = warp_sum(a1);
    if (lane == 0) {
        float l0 = v0 ? a0 + out_b[row0] : -INFINITY;
        float l1 = v1 ? a1 + out_b[row1] : -INFINITY;
        if (v0) g_logits[row0] = l0;
        if (v1) g_logits[row1] = l1;
        slog[warp * 2]     = l0;
        slog[warp * 2 + 1] = l1;
    }
    __syncthreads();
    __shared__ unsigned is_last;
    if (threadIdx.x == 0) {
        float m = slog[0];
        #pragma unroll
        for (int k = 1; k < OUT_ROWS; k++) m = fmaxf(m, slog[k]);
        float s = 0.f;
        #pragma unroll
        for (int k = 0; k < OUT_ROWS; k++) s += expf(slog[k] - m);
        g_bmax[blockIdx.x] = m;
        g_bsum[blockIdx.x] = s;
        __threadfence();
        is_last = (atomicAdd(&g_ctr_out, 1u) == GOUT - 1);
    }
    __syncthreads();
    if (!is_last) return;

    // ---- last block: reduce 3142 (max,sum) pairs ----
    __threadfence();
    int t = threadIdx.x;
    float m = -INFINITY;
    for (int k = t; k < GOUT; k += 256) m = fmaxf(m, g_bmax[k]);
    __shared__ float sred[8];
    m = warp_max(m);
    if (lane == 0) sred[warp] = m;
    __syncthreads();
    if (t == 0) {
        float mm = sred[0];
        #pragma unroll
        for (int k = 1; k < 8; k++) mm = fmaxf(mm, sred[k]);
        sred[0] = mm;
    }
    __syncthreads();
    m = sred[0];
    __syncthreads();
    float s = 0.f;
    for (int k = t; k < GOUT; k += 256) s += g_bsum[k] * expf(g_bmax[k] - m);
    s = warp_sum(s);
    if (lane == 0) sred[warp] = s;
    __syncthreads();
    if (t == 0) {
        float ss = 0.f;
        #pragma unroll
        for (int k = 0; k < 8; k++) ss += sred[k];
        g_logZ = m + logf(ss);
        g_ctr_out = 0;   // reset for next graph replay
    }
}

__global__ void k_final(float* __restrict__ out) {
    int v = blockIdx.x * blockDim.x + threadIdx.x;
    if (v >= V) return;
    out[v] = g_logits[v] - g_logZ;
}

extern "C" void kernel_launch(void* const* d_in, const int* in_sizes, int n_in,
                              void* d_out, int out_size) {
    const int*   tokens = (const int*)  d_in[0];
    const float* h0     = (const float*)d_in[1];
    const float* c0     = (const float*)d_in[2];
    const float* enc    = (const float*)d_in[3];
    const float* emb    = (const float*)d_in[4];
    const float* attn_W = (const float*)d_in[5];
    const float* attn_b = (const float*)d_in[6];
    const float* comb_W = (const float*)d_in[7];
    const float* comb_b = (const float*)d_in[8];
    const float* W_ih   = (const float*)d_in[9];
    const float* W_hh   = (const float*)d_in[10];
    const float* b_ih   = (const float*)d_in[11];
    const float* b_hh   = (const float*)d_in[12];
    const float* out_W  = (const float*)d_in[13];
    const float* out_b  = (const float*)d_in[14];

    float* out    = (float*)d_out;          // [V] log-probs
    float* h_out  = out + V;                // [H]
    float* c_out  = out + V + H;            // [H]
    float* aw_out = out + V + 2 * H;        // [L]

    k_attn        <<<L, 256>>>(tokens, emb, h0, attn_W, attn_b, aw_out);
    k_attn_applied<<<H / 32, 256>>>(enc);
    k_comb        <<<H / 8, 256>>>(tokens, emb, comb_W, comb_b);
    k_lstm        <<<H, 128>>>(W_ih, W_hh, b_ih, b_hh, h0, c0, h_out, c_out);
    k_out         <<<GOUT, 256>>>(out_W, out_b);
    k_final       <<<(V + 511) / 512, 512>>>(out);
}